// round 17
// baseline (speedup 1.0000x reference)
#include <cuda_runtime.h>
#include <math.h>

#define BB 8
#define VV 6890
#define FF 13776
#define NP 4096
#define EPSF 1e-12f
#define NC4 (FF / 4)                 // 3444 coarse CDF entries (stride 4)
#define NFB ((BB * FF + 255) / 256)  // 431 k_faces blocks
#define RBLK 64                      // row blocks per batch (4096/64)
#define NPOST ((5 * BB * NP) / 256)  // 640 k_post blocks (rows + 4x cols)

typedef unsigned long long ull;

// ---------------- device scratch (no allocations allowed) ----------------
__device__ float        g_cdf[BB * FF];            // per-face area -> CDF
__device__ float4       g_fn [BB * FF];            // per-face unit normals
__device__ float4       g_pts[2 * BB * NP];        // sampled points, w=|p|^2
__device__ float4       g_nrm[2 * BB * NP];        // sampled normals
__device__ unsigned int g_rowm[BB * NP];           // per-row mangled min (bits)
__device__ float        g_colp[BB * RBLK * NP];    // col-min partials (8.4MB)
__device__ float        g_edge[NFB];               // edge-loss block partials
__device__ float        g_part[2 * NPOST];         // k_post block partials (d,n)
__device__ unsigned int g_cnt;                     // last-block ticket (self-reset)

// ---------------- packed f32x2 helpers ----------------
__device__ __forceinline__ ull pk2(float lo, float hi) {
    ull r;
    asm("mov.b64 %0, {%1, %2};" : "=l"(r) : "f"(lo), "f"(hi));
    return r;
}
__device__ __forceinline__ float2 unpk(ull v) {
    float2 f;
    asm("mov.b64 {%0, %1}, %2;" : "=f"(f.x), "=f"(f.y) : "l"(v));
    return f;
}
__device__ __forceinline__ ull fma2(ull a, ull b, ull c) {
    ull d;
    asm("fma.rn.f32x2 %0, %1, %2, %3;" : "=l"(d) : "l"(a), "l"(b), "l"(c));
    return d;
}
__device__ __forceinline__ ull add2(ull a, ull b) {
    ull d;
    asm("add.rn.f32x2 %0, %1, %2;" : "=l"(d) : "l"(a), "l"(b));
    return d;
}
// packed min emulated with two scalar FMNMX on the register-pair halves
__device__ __forceinline__ ull min2(ull a, ull b) {
    float2 fa = unpk(a), fb = unpk(b);
    return pk2(fminf(fa.x, fb.x), fminf(fa.y, fb.y));
}
__device__ __forceinline__ ull shfl_xor64_w8(ull v, int m) {
    unsigned lo = (unsigned)v, hi = (unsigned)(v >> 32);
    lo = __shfl_xor_sync(0xffffffffu, lo, m, 8);
    hi = __shfl_xor_sync(0xffffffffu, hi, m, 8);
    return ((ull)hi << 32) | lo;
}

// ---------------- kernels ----------------

// Per (b,f): area, unit normal, edge partial per block.
__global__ void k_faces(const float* __restrict__ verts,
                        const int*   __restrict__ faces) {
    int id = blockIdx.x * blockDim.x + threadIdx.x;
    float esum = 0.f;
    if (id < BB * FF) {
        int b = id / FF, f = id % FF;
        int i0 = faces[f * 3 + 0];
        int i1 = faces[f * 3 + 1];
        int i2 = faces[f * 3 + 2];
        const float* vb = verts + (size_t)b * VV * 3;
        float ax = vb[i0*3+0], ay = vb[i0*3+1], az = vb[i0*3+2];
        float bx = vb[i1*3+0], by = vb[i1*3+1], bz = vb[i1*3+2];
        float cx = vb[i2*3+0], cy = vb[i2*3+1], cz = vb[i2*3+2];
        float ux = bx-ax, uy = by-ay, uz = bz-az;   // v1-v0
        float wx = cx-ax, wy = cy-ay, wz = cz-az;   // v2-v0
        float crx = uy*wz - uz*wy;
        float cry = uz*wx - ux*wz;
        float crz = ux*wy - uy*wx;
        float cn  = sqrtf(crx*crx + cry*cry + crz*crz);
        g_cdf[id] = 0.5f * cn;
        float inv = 1.f / (cn + EPSF);
        g_fn[id]  = make_float4(crx*inv, cry*inv, crz*inv, 0.f);
        float ex = bx-cx, ey = by-cy, ez = bz-cz;   // v1-v2
        esum = (ux*ux + uy*uy + uz*uz)
             + (ex*ex + ey*ey + ez*ez)
             + (wx*wx + wy*wy + wz*wz);
    }
    __shared__ float sred[256];
    sred[threadIdx.x] = esum;
    __syncthreads();
    for (int s = 128; s > 0; s >>= 1) {
        if (threadIdx.x < s) sred[threadIdx.x] += sred[threadIdx.x + s];
        __syncthreads();
    }
    if (threadIdx.x == 0) g_edge[blockIdx.x] = sred[0];
}

// Per-batch inclusive scan of areas -> normalized CDF. One block per batch.
__global__ void k_scan() {
    const int CH = (FF + 1023) / 1024;     // 14
    int b = blockIdx.x;
    int t = threadIdx.x;
    int lane = t & 31, warp = t >> 5;      // 32 warps
    float* a = g_cdf + (size_t)b * FF;
    int beg = t * CH;
    int end = min(beg + CH, FF);
    float loc[CH];
    float s = 0.f;
    for (int i = beg; i < end; i++) { s += a[i]; loc[i - beg] = s; }

    float ws = s;
    #pragma unroll
    for (int off = 1; off < 32; off <<= 1) {
        float v = __shfl_up_sync(0xffffffffu, ws, off);
        if (lane >= off) ws += v;
    }
    __shared__ float wsum[32];
    __shared__ float wpre[33];
    if (lane == 31) wsum[warp] = ws;
    __syncthreads();
    if (warp == 0) {
        float xs = wsum[lane];
        #pragma unroll
        for (int off = 1; off < 32; off <<= 1) {
            float v = __shfl_up_sync(0xffffffffu, xs, off);
            if (lane >= off) xs += v;
        }
        wpre[lane + 1] = xs;
        if (lane == 0) wpre[0] = 0.f;
    }
    __syncthreads();
    float total = wpre[32];
    float excl  = wpre[warp] + (ws - s);
    float scale = 1.f / (total + EPSF);
    for (int i = beg; i < end; i++) a[i] = (excl + loc[i - beg]) * scale;
}

// Sample points. grid (16 chunks, 8 batches, 2 sets), block 256.
__global__ void k_sample(const float* __restrict__ verts,
                         const int*   __restrict__ faces,
                         const float* __restrict__ rp,
                         const float* __restrict__ rg) {
    int set = blockIdx.z;
    int b   = blockIdx.y;
    int n   = blockIdx.x * 256 + threadIdx.x;
    const float* cdf = g_cdf + (size_t)b * FF;
    __shared__ float sc[NC4];
    for (int i = threadIdx.x; i < NC4; i += 256)
        sc[i] = cdf[i * 4 + 3];
    __syncthreads();

    const float* rnd = (set ? rg : rp) + ((size_t)b * NP + n) * 3;
    float u = rnd[0], r1 = rnd[1], r2 = rnd[2];

    int lo = 0, hi = NC4;
    while (lo < hi) {
        int m = (lo + hi) >> 1;
        if (sc[m] < u) lo = m + 1; else hi = m;
    }
    int idx;
    if (lo == NC4) {
        idx = FF - 1;
    } else {
        float4 seg = *(const float4*)&cdf[lo * 4];
        idx = lo * 4 + (seg.x < u) + (seg.y < u) + (seg.z < u);
    }
    int i0 = faces[idx*3+0], i1 = faces[idx*3+1], i2 = faces[idx*3+2];
    const float* vb = verts + (size_t)b * VV * 3;
    float su = sqrtf(r1);
    float w0 = 1.f - su;
    float w1 = su * (1.f - r2);
    float w2 = su * r2;
    float x = w0*vb[i0*3+0] + w1*vb[i1*3+0] + w2*vb[i2*3+0];
    float y = w0*vb[i0*3+1] + w1*vb[i1*3+1] + w2*vb[i2*3+1];
    float z = w0*vb[i0*3+2] + w1*vb[i1*3+2] + w2*vb[i2*3+2];
    int out = set * BB * NP + b * NP + n;
    g_pts[out] = make_float4(x, y, z, x*x + y*y + z*z);
    g_nrm[out] = g_fn[(size_t)b * FF + idx];
}

// Fused chamfer, ROW-packed f32x2: each ull lane holds a different row, so
// 8 rows/thread cost the same registers as 4 duplicated rows. q is stored
// duplicated in shared ((q.x,q.x) pairs). Double-buffered tiles, width-8
// shuffle col reduce, one __syncthreads per tile.
// grid (RBLK=64, BB), block 256: 64 rows x 4096 cols per block.
// ty = tid&7 (8 row groups x 8 rows), tx = tid>>3 (32 col groups x 4 cols).
__global__ void __launch_bounds__(256) k_cham() {
    const int b   = blockIdx.y;
    const int rb  = blockIdx.x * 64;
    const int tid = threadIdx.x;
    const int tx  = tid >> 3;      // 0..31 col group
    const int ty  = tid & 7;       // 0..7 row group
    const float4* __restrict__ P = g_pts + (size_t)b * NP;
    const float4* __restrict__ Q = g_pts + BB * NP + (size_t)b * NP;

    __shared__ __align__(16) ull sqx[2][128];   // (q.x, q.x) duplicated pairs
    __shared__ __align__(16) ull sqy[2][128];
    __shared__ __align__(16) ull sqz[2][128];
    __shared__ __align__(16) ull sqw[2][128];
    __shared__ unsigned int srow[64][33];

    const ull INF2 = pk2(__int_as_float(0x7F800000), __int_as_float(0x7F800000));

    ull pxd[4], pyd[4], pzd[4], pwd[4], rowb2[4];
    #pragma unroll
    for (int j = 0; j < 4; j++) {
        float4 p0 = P[rb + ty * 8 + 2 * j];
        float4 p1 = P[rb + ty * 8 + 2 * j + 1];
        pxd[j] = pk2(-2.f * p0.x, -2.f * p1.x);
        pyd[j] = pk2(-2.f * p0.y, -2.f * p1.y);
        pzd[j] = pk2(-2.f * p0.z, -2.f * p1.z);
        pwd[j] = pk2(p0.w, p1.w);
        rowb2[j] = INF2;
    }

    if (tid < 128) {
        float4 q = Q[tid];
        sqx[0][tid] = pk2(q.x, q.x);
        sqy[0][tid] = pk2(q.y, q.y);
        sqz[0][tid] = pk2(q.z, q.z);
        sqw[0][tid] = pk2(q.w, q.w);
    }
    __syncthreads();

    for (int t = 0; t < 32; t++) {
        float4 nq;
        if (t < 31 && tid < 128) nq = Q[(t + 1) * 128 + tid];
        const int cur = t & 1;
        ull colb[4];
        #pragma unroll
        for (int ci = 0; ci < 4; ci++) colb[ci] = INF2;

        #pragma unroll
        for (int ci = 0; ci < 4; ci++) {
            int c = tx * 4 + ci;
            ull qx = sqx[cur][c];
            ull qy = sqy[cur][c];
            ull qz = sqz[cur][c];
            ull qw = sqw[cur][c];
            ull cpk = (ull)(unsigned)(t * 128 + c) * 0x0000000100000001ULL;
            #pragma unroll
            for (int j = 0; j < 4; j++) {
                ull d = add2(fma2(pxd[j], qx,
                          fma2(pyd[j], qy,
                          fma2(pzd[j], qz, qw))), pwd[j]);
                rowb2[j] = min2(rowb2[j], (d & 0xFFFFF000FFFFF000ULL) | cpk);
                colb[ci] = min2(colb[ci], d);
            }
        }
        // fold row-pair halves to scalars, pack 4 cols into 2 ulls
        float2 c0 = unpk(colb[0]), c1 = unpk(colb[1]);
        float2 c2 = unpk(colb[2]), c3 = unpk(colb[3]);
        ull cb0 = pk2(fminf(c0.x, c0.y), fminf(c1.x, c1.y));
        ull cb1 = pk2(fminf(c2.x, c2.y), fminf(c3.x, c3.y));
        // reduce across the 8 ty lanes (consecutive lanes, width 8)
        cb0 = min2(cb0, shfl_xor64_w8(cb0, 4));
        cb0 = min2(cb0, shfl_xor64_w8(cb0, 2));
        cb0 = min2(cb0, shfl_xor64_w8(cb0, 1));
        cb1 = min2(cb1, shfl_xor64_w8(cb1, 4));
        cb1 = min2(cb1, shfl_xor64_w8(cb1, 2));
        cb1 = min2(cb1, shfl_xor64_w8(cb1, 1));
        if (ty == 0) {
            int base = ((b * RBLK + blockIdx.x) << 12) + t * 128 + tx * 4;
            float2 f0 = unpk(cb0), f1 = unpk(cb1);
            *(float4*)&g_colp[base] = make_float4(f0.x, f0.y, f1.x, f1.y);
        }
        if (t < 31 && tid < 128) {
            const int nb = (t + 1) & 1;
            sqx[nb][tid] = pk2(nq.x, nq.x);
            sqy[nb][tid] = pk2(nq.y, nq.y);
            sqz[nb][tid] = pk2(nq.z, nq.z);
            sqw[nb][tid] = pk2(nq.w, nq.w);
        }
        __syncthreads();
    }

    // unpack row-pair mins (two distinct rows per ull), reduce across tx
    #pragma unroll
    for (int j = 0; j < 4; j++) {
        float2 f = unpk(rowb2[j]);
        srow[ty * 8 + 2 * j + 0][tx] = __float_as_uint(f.x);
        srow[ty * 8 + 2 * j + 1][tx] = __float_as_uint(f.y);
    }
    __syncthreads();
    if (tid < 64) {
        float best = __uint_as_float(srow[tid][0]);
        #pragma unroll
        for (int k = 1; k < 32; k++)
            best = fminf(best, __uint_as_float(srow[tid][k]));
        g_rowm[(size_t)b * NP + rb + tid] = __float_as_uint(best);
    }
}

// Rows: decode argmin, recompute exact distance + normal loss.
// Cols: quarter-per-warp mapping (1 cache line per warp load), 8 independent
// accumulators over 16 partials, cross-quarter fold via smem.
__global__ void k_post(float* out) {
    int gid = blockIdx.x * 256 + threadIdx.x;   // 0 .. 5*BB*NP
    float sd = 0.f, sn = 0.f;
    if (gid < BB * NP) {                        // rows -> dist1 + normals
        int b = gid >> 12;
        unsigned int m = g_rowm[gid];
        int col = m & 0xFFF;
        int qi  = BB * NP + (b << 12) + col;
        float4 p = g_pts[gid];
        float4 q = g_pts[qi];
        sd = p.w + q.w - 2.f * (p.x*q.x + p.y*q.y + p.z*q.z);
        float4 pn = g_nrm[gid];
        float4 qn = g_nrm[qi];
        sn = 1.f - fabsf(pn.x*qn.x + pn.y*qn.y + pn.z*qn.z);
    } else {                                    // cols -> dist2
        int lane = threadIdx.x & 31;
        int wb   = threadIdx.x >> 5;            // warp in block 0..7
        int w    = (gid - BB * NP) >> 5;        // global col-warp
        int group = w >> 2;                     // 0..1023 (32-col groups)
        int q     = wb & 3;                     // quarter (w&3 == wb&3)
        int flat  = group * 32 + lane;          // column (batch-flattened)
        int b = flat >> 12, col = flat & 4095;
        const float* cp = g_colp + ((size_t)(b * RBLK + q * 16) << 12) + col;
        float m0 = __int_as_float(0x7F800000), m1 = m0, m2 = m0, m3 = m0;
        float m4 = m0, m5 = m0, m6 = m0, m7 = m0;
        #pragma unroll
        for (int k = 0; k < 16; k += 8) {
            m0 = fminf(m0, cp[(size_t)(k + 0) << 12]);
            m1 = fminf(m1, cp[(size_t)(k + 1) << 12]);
            m2 = fminf(m2, cp[(size_t)(k + 2) << 12]);
            m3 = fminf(m3, cp[(size_t)(k + 3) << 12]);
            m4 = fminf(m4, cp[(size_t)(k + 4) << 12]);
            m5 = fminf(m5, cp[(size_t)(k + 5) << 12]);
            m6 = fminf(m6, cp[(size_t)(k + 6) << 12]);
            m7 = fminf(m7, cp[(size_t)(k + 7) << 12]);
        }
        float best = fminf(fminf(fminf(m0, m1), fminf(m2, m3)),
                           fminf(fminf(m4, m5), fminf(m6, m7)));
        __shared__ float sq[8][32];
        sq[wb][lane] = best;
        __syncthreads();
        if (q == 0) {
            int wg = wb & 4;                    // group base warp (0 or 4)
            sd = fminf(fminf(sq[wg][lane], sq[wg + 1][lane]),
                       fminf(sq[wg + 2][lane], sq[wg + 3][lane]));
        }
    }
    __shared__ float rA[256];
    __shared__ float rB[256];
    rA[threadIdx.x] = sd;
    rB[threadIdx.x] = sn;
    __syncthreads();
    for (int s = 128; s > 0; s >>= 1) {
        if (threadIdx.x < s) {
            rA[threadIdx.x] += rA[threadIdx.x + s];
            rB[threadIdx.x] += rB[threadIdx.x + s];
        }
        __syncthreads();
    }
    __shared__ bool amlast;
    if (threadIdx.x == 0) {
        g_part[blockIdx.x * 2 + 0] = rA[0];
        g_part[blockIdx.x * 2 + 1] = rB[0];
        __threadfence();
        unsigned int tkt = atomicAdd(&g_cnt, 1u);
        amlast = (tkt == gridDim.x - 1);
    }
    __syncthreads();
    if (!amlast) return;

    // last block: fold NPOST block partials + 431 edge partials
    int t = threadIdx.x;
    float fd = g_part[t * 2] + g_part[(t + 256) * 2]
             + (t + 512 < NPOST ? g_part[(t + 512) * 2] : 0.f);
    float fn = g_part[t * 2 + 1] + g_part[(t + 256) * 2 + 1]
             + (t + 512 < NPOST ? g_part[(t + 512) * 2 + 1] : 0.f);
    float fe = (t < NFB ? g_edge[t] : 0.f) + (t + 256 < NFB ? g_edge[t + 256] : 0.f);
    rA[t] = fd; rB[t] = fn;
    __shared__ float rC[256];
    rC[t] = fe;
    __syncthreads();
    for (int s = 128; s > 0; s >>= 1) {
        if (t < s) { rA[t] += rA[t+s]; rB[t] += rB[t+s]; rC[t] += rC[t+s]; }
        __syncthreads();
    }
    if (t == 0) {
        double invBN = 1.0 / (double)(BB * NP);
        double cham  = (double)rA[0] * invBN;
        double nrm   = (double)rB[0] * invBN;
        double edge  = (double)rC[0] / (3.0 * (double)(BB * FF));
        out[0] = (float)(1.0 * cham + 0.1 * nrm + 0.5 * edge);
        g_cnt = 0;                   // reset for next graph replay
    }
}

// ---------------- launch ----------------
extern "C" void kernel_launch(void* const* d_in, const int* in_sizes, int n_in,
                              void* d_out, int out_size) {
    const float* pv = (const float*)d_in[0];   // predicted_vertices (B,V,3)
    const int*   pf = (const int*)  d_in[1];   // predicted_faces (F,3)
    // d_in[2], d_in[3] (gt mesh) unused by the reference computation
    const float* rp = (const float*)d_in[4];   // rand_pred (B,N,3)
    const float* rg = (const float*)d_in[5];   // rand_gt   (B,N,3)

    k_faces<<<NFB, 256>>>(pv, pf);
    k_scan<<<BB, 1024>>>();
    k_sample<<<dim3(16, BB, 2), 256>>>(pv, pf, rp, rg);
    k_cham<<<dim3(RBLK, BB), 256>>>();
    k_post<<<NPOST, 256>>>((float*)d_out);
}